// round 14
// baseline (speedup 1.0000x reference)
#include <cuda_runtime.h>
#include <cuda_bf16.h>
#include <math.h>

#define Bdim 4
#define Ldim 2048
#define Cdim 1024
#define Hdim 16
#define Mdim (Bdim*Ldim)          // 8192
#define MAX_SCALE_MUL 4.605170185988091f   // log(100)
#define BHL (Bdim*Hdim*Ldim)      // 131072

// ---- scratch (__device__ globals; allocation-free rule) ----
__device__ unsigned g_xhi   [Mdim*512],  g_xlo   [Mdim*512];
__device__ unsigned g_wqkvhi[3072*512],  g_wqkvlo[3072*512];
__device__ unsigned g_wprohi[1024*512],  g_wprolo[1024*512];
__device__ unsigned g_ctxhi [Mdim*512],  g_ctxlo [Mdim*512];
__device__ float g_q  [BHL*64];   // [b,h,l,d] fp32
__device__ float g_k  [BHL*64];
__device__ float g_vt [BHL*64];   // [b,h,d,l] fp32

// ============================================================
// helpers
// ============================================================
__device__ __forceinline__ void split2(float x0, float x1, unsigned &hi, unsigned &lo) {
    __nv_bfloat162 h2 = __floats2bfloat162_rn(x0, x1);
    float hx = __bfloat162float(h2.x), hy = __bfloat162float(h2.y);
    __nv_bfloat162 l2 = __floats2bfloat162_rn(x0 - hx, x1 - hy);
    hi = *reinterpret_cast<unsigned*>(&h2);
    lo = *reinterpret_cast<unsigned*>(&l2);
}

// NOTE: non-volatile — pure function of inputs; lets ptxas schedule MMAs.
__device__ __forceinline__ void mma16816(float* c, const unsigned* a, const unsigned* b) {
    asm("mma.sync.aligned.m16n8k16.row.col.f32.bf16.bf16.f32 "
        "{%0,%1,%2,%3},{%4,%5,%6,%7},{%8,%9},{%0,%1,%2,%3};\n"
        : "+f"(c[0]), "+f"(c[1]), "+f"(c[2]), "+f"(c[3])
        : "r"(a[0]), "r"(a[1]), "r"(a[2]), "r"(a[3]), "r"(b[0]), "r"(b[1]));
}

__device__ __forceinline__ void ldsm4(unsigned &d0, unsigned &d1, unsigned &d2, unsigned &d3,
                                      unsigned addr) {
    asm volatile("ldmatrix.sync.aligned.m8n8.x4.shared.b16 {%0,%1,%2,%3}, [%4];"
        : "=r"(d0), "=r"(d1), "=r"(d2), "=r"(d3) : "r"(addr));
}

__device__ __forceinline__ void cpa16(unsigned dst, const void* src) {
    asm volatile("cp.async.cg.shared.global [%0], [%1], 16;" :: "r"(dst), "l"(src) : "memory");
}
__device__ __forceinline__ void cpa_commit() { asm volatile("cp.async.commit_group;" ::: "memory"); }
__device__ __forceinline__ void cpa_wait0()  { asm volatile("cp.async.wait_group 0;" ::: "memory"); }
__device__ __forceinline__ void cpa_wait1()  { asm volatile("cp.async.wait_group 1;" ::: "memory"); }

// ============================================================
// elementwise fp32 -> packed bf16 hi/lo split
// ============================================================
__global__ __launch_bounds__(256) void split_ker(
    const float* __restrict__ src, unsigned* __restrict__ hi,
    unsigned* __restrict__ lo, int n4)
{
    int i = blockIdx.x * 256 + threadIdx.x;
    if (i < n4) {
        float4 v = ((const float4*)src)[i];
        unsigned h0,l0,h1,l1;
        split2(v.x, v.y, h0, l0);
        split2(v.z, v.w, h1, l1);
        ((uint2*)hi)[i] = make_uint2(h0, h1);
        ((uint2*)lo)[i] = make_uint2(l0, l1);
    }
}

// ============================================================
// GEMM: C[M,N] = A[M,1024].W[N,1024]^T  (pre-split operands)
// CTA 128x128, BK=32, 2-stage cp.async, 8 warps (2M x 4N), 2 CTA/SM.
// Stage (40KB): Ahi@0 | Alo@10240 | Whi@20480 | Wlo@30720
// Rows padded to 80B: ldmatrix conflict-free without swizzle.
// MMA stream = 3 passes of 16 independent accumulators each.
// ============================================================
__device__ __forceinline__ void gemm_issue_tile(
    const unsigned* __restrict__ Ah, const unsigned* __restrict__ Al,
    const unsigned* __restrict__ Wh, const unsigned* __restrict__ Wl,
    int bm, int bn, int kt, unsigned sb, int tid)
{
    const int r  = tid >> 1;          // 0..127
    const int ku = kt * 16;           // u32 col offset (BK=32 = 16 u32)
    const unsigned* g0 = Ah + (size_t)(bm + r)*512 + ku;
    const unsigned* g1 = Al + (size_t)(bm + r)*512 + ku;
    const unsigned* g2 = Wh + (size_t)(bn + r)*512 + ku;
    const unsigned* g3 = Wl + (size_t)(bn + r)*512 + ku;
#pragma unroll
    for (int c = 0; c < 2; c++) {
        int cc = (tid & 1)*2 + c;     // chunk 0..3
        unsigned off = (unsigned)(r*80 + cc*16);
        cpa16(sb + off,          g0 + cc*4);
        cpa16(sb + 10240u + off, g1 + cc*4);
        cpa16(sb + 20480u + off, g2 + cc*4);
        cpa16(sb + 30720u + off, g3 + cc*4);
    }
}

template<int MODE>
__global__ __launch_bounds__(256, 2) void gemm_ker(
    const unsigned* __restrict__ Ahg, const unsigned* __restrict__ Alg,
    const unsigned* __restrict__ Whg, const unsigned* __restrict__ Wlg,
    const float* __restrict__ bq, const float* __restrict__ bv,
    float* __restrict__ out)
{
    extern __shared__ unsigned smg[];
    const int tid  = threadIdx.x;
    const int lane = tid & 31;
    const int wid  = tid >> 5;
    const int wm   = wid >> 2, wn = wid & 3;
    const int qr   = lane >> 2, qc = lane & 3;
    const int j    = lane >> 3, rr = lane & 7;   // ldsm lane decomposition
    const int bm = blockIdx.y * 128, bn = blockIdx.x * 128;
    const unsigned smbase = (unsigned)__cvta_generic_to_shared(smg);

    unsigned a_off[4], b_off[2];
#pragma unroll
    for (int mt = 0; mt < 4; mt++)
        a_off[mt] = (unsigned)((wm*64 + mt*16 + ((j & 1) << 3) + rr) * 80 + (j >> 1)*16);
#pragma unroll
    for (int p = 0; p < 2; p++)
        b_off[p] = (unsigned)((wn*32 + p*16 + ((j >> 1) << 3) + rr) * 80 + (j & 1)*16);

    float acc[4][4][4];
#pragma unroll
    for (int i = 0; i < 4; i++)
#pragma unroll
        for (int jj = 0; jj < 4; jj++)
#pragma unroll
            for (int t = 0; t < 4; t++) acc[i][jj][t] = 0.f;

    gemm_issue_tile(Ahg, Alg, Whg, Wlg, bm, bn, 0, smbase, tid);
    cpa_commit();

    for (int kt = 0; kt < 32; kt++) {
        if (kt + 1 < 32) {
            gemm_issue_tile(Ahg, Alg, Whg, Wlg, bm, bn, kt + 1,
                            smbase + ((kt + 1) & 1) * 40960u, tid);
            cpa_commit();
            cpa_wait1();
        } else {
            cpa_wait0();
        }
        __syncthreads();

        const unsigned sA = smbase + (unsigned)(kt & 1) * 40960u;
        const unsigned sW = sA + 20480u;
#pragma unroll
        for (int ks = 0; ks < 2; ks++) {
            const unsigned ko = (unsigned)(ks * 32);
            unsigned ah[4][4], al[4][4], bh[4][2], bl[4][2];
#pragma unroll
            for (int mt = 0; mt < 4; mt++) {
                ldsm4(ah[mt][0], ah[mt][1], ah[mt][2], ah[mt][3], sA + a_off[mt] + ko);
                ldsm4(al[mt][0], al[mt][1], al[mt][2], al[mt][3], sA + 10240u + a_off[mt] + ko);
            }
#pragma unroll
            for (int p = 0; p < 2; p++) {
                ldsm4(bh[2*p][0], bh[2*p][1], bh[2*p+1][0], bh[2*p+1][1], sW + b_off[p] + ko);
                ldsm4(bl[2*p][0], bl[2*p][1], bl[2*p+1][0], bl[2*p+1][1], sW + 10240u + b_off[p] + ko);
            }
            // 3 passes x 16 independent accumulators (per-acc order: bl, al*bh, ah*bh)
#pragma unroll
            for (int mt = 0; mt < 4; mt++)
#pragma unroll
                for (int nt = 0; nt < 4; nt++)
                    mma16816(acc[mt][nt], ah[mt], bl[nt]);
#pragma unroll
            for (int mt = 0; mt < 4; mt++)
#pragma unroll
                for (int nt = 0; nt < 4; nt++)
                    mma16816(acc[mt][nt], al[mt], bh[nt]);
#pragma unroll
            for (int mt = 0; mt < 4; mt++)
#pragma unroll
                for (int nt = 0; nt < 4; nt++)
                    mma16816(acc[mt][nt], ah[mt], bh[nt]);
        }
        __syncthreads();
    }

    if (MODE == 1) {
#pragma unroll
        for (int mt = 0; mt < 4; mt++)
#pragma unroll
            for (int nt = 0; nt < 4; nt++) {
                int m = bm + wm*64 + mt*16 + qr;
                int n = bn + wn*32 + nt*8 + qc*2;
                float b0 = bq[n], b1 = bq[n+1];
                *(float2*)(out + (size_t)m*Cdim + n)
                    = make_float2(acc[mt][nt][0] + b0, acc[mt][nt][1] + b1);
                *(float2*)(out + (size_t)(m+8)*Cdim + n)
                    = make_float2(acc[mt][nt][2] + b0, acc[mt][nt][3] + b1);
            }
    } else {
        const int which = bn >> 10;        // 0:q 1:k 2:v
        const int cb = bn & 1023;
#pragma unroll
        for (int mt = 0; mt < 4; mt++)
#pragma unroll
            for (int nt = 0; nt < 4; nt++) {
                int nloc = wn*32 + nt*8 + qc*2;
                int ncol = cb + nloc;
                int h = ncol >> 6, d = ncol & 63;
                float b0 = 0.f, b1 = 0.f;
                if (which == 0) { b0 = bq[ncol]; b1 = bq[ncol+1]; }
                if (which == 2) { b0 = bv[ncol]; b1 = bv[ncol+1]; }
#pragma unroll
                for (int hh = 0; hh < 2; hh++) {
                    int m = bm + wm*64 + mt*16 + qr + hh*8;
                    int b = m >> 11, l = m & (Ldim - 1);
                    float v0 = acc[mt][nt][hh*2]   + b0;
                    float v1 = acc[mt][nt][hh*2+1] + b1;
                    if (which == 2) {
                        size_t base = ((size_t)(b*Hdim + h)*64 + d)*Ldim + l;
                        g_vt[base]        = v0;
                        g_vt[base + Ldim] = v1;
                    } else {
                        float* dst = (which == 0) ? g_q : g_k;
                        *(float2*)(dst + ((size_t)(b*Hdim + h)*Ldim + l)*64 + d)
                            = make_float2(v0, v1);
                    }
                }
            }
    }
}

// ============================================================
// L2-normalize q,k rows (fp32 in place); q *= exp(min(sml[h],log100))
// ============================================================
__global__ __launch_bounds__(256) void norm_kernel(const float* __restrict__ sml)
{
    const int NR = BHL;
    int w = blockIdx.x * 8 + (threadIdx.x >> 5);
    int lane = threadIdx.x & 31;
    bool is_q = (w < NR);
    float* p = is_q ? g_q : g_k;
    int r = is_q ? w : (w - NR);
    float a0 = p[(size_t)r*64 + lane];
    float a1 = p[(size_t)r*64 + lane + 32];
    float s = a0*a0 + a1*a1;
#pragma unroll
    for (int off = 16; off > 0; off >>= 1)
        s += __shfl_xor_sync(0xffffffffu, s, off);
    float mul = 1.0f;
    if (is_q) {
        int h = (r >> 11) & (Hdim - 1);
        mul = __expf(fminf(sml[h], MAX_SCALE_MUL));
    }
    float inv = mul / fmaxf(sqrtf(s), 1e-12f);
    p[(size_t)r*64 + lane]      = a0 * inv;
    p[(size_t)r*64 + lane + 32] = a1 * inv;
}

// ============================================================
// attention tile loaders (fp32 -> split -> swizzled smem)
// ============================================================
__device__ __forceinline__ void load_tile_128x64_f32(
    const float* __restrict__ src, size_t row0,
    unsigned* __restrict__ Hi, unsigned* __restrict__ Lo, int tid)
{
#pragma unroll
    for (int p = 0; p < 8; p++) {
        int r = p*16 + (tid >> 4);
        int jj = tid & 15;
        const float4 v = *(const float4*)(src + (row0 + r)*64 + jj*4);
        unsigned h0,l0,h1,l1;
        split2(v.x, v.y, h0, l0);
        split2(v.z, v.w, h1, l1);
        int c = (2*jj) ^ ((r & 7) << 2);
        *(uint2*)&Hi[r*32 + c] = make_uint2(h0, h1);
        *(uint2*)&Lo[r*32 + c] = make_uint2(l0, l1);
    }
}

__device__ __forceinline__ void load_vt_tile_f32(
    const float* __restrict__ Vg, int l0,
    unsigned* __restrict__ Hi, unsigned* __restrict__ Lo, int tid)
{
#pragma unroll
    for (int p = 0; p < 8; p++) {
        int r = p*8 + (tid >> 5);
        int jj = tid & 31;
        const float4 v = *(const float4*)(Vg + (size_t)r*Ldim + l0 + jj*4);
        unsigned h0,l0_,h1,l1;
        split2(v.x, v.y, h0, l0_);
        split2(v.z, v.w, h1, l1);
        int c = (2*jj) ^ ((r & 7) << 2);
        *(uint2*)&Hi[r*64 + c] = make_uint2(h0, h1);
        *(uint2*)&Lo[r*64 + c] = make_uint2(l0_, l1);
    }
}

// ============================================================
// Flash attention — R6 loaders/softmax; MMA streams restructured
// into 3 passes of 8 independent accumulators (dep distance 8).
// Block = (b,h) x 128-query tile, 8 warps, 96KB smem.
// smem u32: Qhi@0 Qlo@4096 Khi@8192 Klo@12288 Vhi@16384 Vlo@20480
// ============================================================
__global__ __launch_bounds__(256) void attn_ker()
{
    extern __shared__ unsigned sma[];
    unsigned *Qhi = sma,          *Qlo = sma + 4096;
    unsigned *Khi = sma + 8192,   *Klo = sma + 12288;
    unsigned *Vhi = sma + 16384,  *Vlo = sma + 20480;

    const int tid = threadIdx.x, lane = tid & 31, wid = tid >> 5;
    const int qr = lane >> 2, qc = lane & 3;
    const int bh = blockIdx.y, q0 = blockIdx.x * 128;
    const float* Qg = g_q  + (size_t)bh * Ldim * 64;
    const float* Kg = g_k  + (size_t)bh * Ldim * 64;
    const float* Vg = g_vt + (size_t)bh * 64 * Ldim;

    load_tile_128x64_f32(Qg, q0, Qhi, Qlo, tid);

    float oacc[8][4];
#pragma unroll
    for (int i = 0; i < 8; i++)
#pragma unroll
        for (int t = 0; t < 4; t++) oacc[i][t] = 0.f;
    float mrow[2] = {-1e30f, -1e30f}, lrow[2] = {0.f, 0.f};

    for (int kt = 0; kt < Ldim/128; kt++) {
        __syncthreads();
        load_tile_128x64_f32(Kg, (size_t)kt*128, Khi, Klo, tid);
        load_vt_tile_f32(Vg, kt*128, Vhi, Vlo, tid);
        __syncthreads();

        // ---- S = Q . K^T  (16 q rows x 128 keys per warp) ----
        float sacc[16][4];
#pragma unroll
        for (int i = 0; i < 16; i++)
#pragma unroll
            for (int t = 0; t < 4; t++) sacc[i][t] = 0.f;
#pragma unroll
        for (int ks = 0; ks < 4; ks++) {
            const int c0 = ks*8 + qc, c1 = c0 + 4, sw = qr << 2;
            int r0 = wid*16 + qr, r1 = r0 + 8;
            int i0 = r0*32 + (c0^sw), i1 = r1*32 + (c0^sw);
            int i2 = r0*32 + (c1^sw), i3 = r1*32 + (c1^sw);
            unsigned ah[4] = {Qhi[i0], Qhi[i1], Qhi[i2], Qhi[i3]};
            unsigned al[4] = {Qlo[i0], Qlo[i1], Qlo[i2], Qlo[i3]};
#pragma unroll
            for (int g = 0; g < 2; g++) {
                unsigned bb[8][2];
                // pass 1: ah * K_lo
#pragma unroll
                for (int t = 0; t < 8; t++) {
                    int n0 = (g*8 + t)*8 + qr;
                    bb[t][0] = Klo[n0*32 + (c0^sw)];
                    bb[t][1] = Klo[n0*32 + (c1^sw)];
                }
#pragma unroll
                for (int t = 0; t < 8; t++) mma16816(sacc[g*8+t], ah, bb[t]);
                // passes 2+3: al * K_hi, ah * K_hi
#pragma unroll
                for (int t = 0; t < 8; t++) {
                    int n0 = (g*8 + t)*8 + qr;
                    bb[t][0] = Khi[n0*32 + (c0^sw)];
                    bb[t][1] = Khi[n0*32 + (c1^sw)];
                }
#pragma unroll
                for (int t = 0; t < 8; t++) mma16816(sacc[g*8+t], al, bb[t]);
#pragma unroll
                for (int t = 0; t < 8; t++) mma16816(sacc[g*8+t], ah, bb[t]);
            }
        }

        // ---- online softmax (quad reduce) ----
#pragma unroll
        for (int hh = 0; hh < 2; hh++) {
            float mx = -1e30f;
#pragma unroll
            for (int nt = 0; nt < 16; nt++)
                mx = fmaxf(mx, fmaxf(sacc[nt][hh*2], sacc[nt][hh*2+1]));
            mx = fmaxf(mx, __shfl_xor_sync(0xffffffffu, mx, 1));
            mx = fmaxf(mx, __shfl_xor_sync(0xffffffffu, mx, 2));
            float mnew = fmaxf(mrow[hh], mx);
            float corr = __expf(mrow[hh] - mnew);
            float rs = 0.f;
#pragma unroll
            for (int nt = 0; nt < 16; nt++) {
                float e0 = __expf(sacc[nt][hh*2]   - mnew);
                float e1 = __expf(sacc[nt][hh*2+1] - mnew);
                sacc[nt][hh*2] = e0; sacc[nt][hh*2+1] = e1;
                rs += e0 + e1;
            }
            rs += __shfl_xor_sync(0xffffffffu, rs, 1);
            rs += __shfl_xor_sync(0xffffffffu, rs, 2);
            mrow[hh] = mnew;
            lrow[hh] = lrow[hh]*corr + rs;
#pragma unroll
            for (int nt = 0; nt < 8; nt++) {
                oacc[nt][hh*2]   *= corr;
                oacc[nt][hh*2+1] *= corr;
            }
        }

        // ---- O += P . V  (P from sacc regs; 3 passes x 8 accs) ----
#pragma unroll
        for (int ks = 0; ks < 8; ks++) {
            unsigned ah[4], al[4];
            split2(sacc[2*ks][0],   sacc[2*ks][1],   ah[0], al[0]);
            split2(sacc[2*ks][2],   sacc[2*ks][3],   ah[1], al[1]);
            split2(sacc[2*ks+1][0], sacc[2*ks+1][1], ah[2], al[2]);
            split2(sacc[2*ks+1][2], sacc[2*ks+1][3], ah[3], al[3]);
            const int c0 = ks*8 + qc, c1 = c0 + 4, sw = qr << 2;
            unsigned bb[8][2];
            // pass 1: P_hi * V_lo
#pragma unroll
            for (int nt = 0; nt < 8; nt++) {
                int n0 = nt*8 + qr;
                bb[nt][0] = Vlo[n0*64 + (c0^sw)];
                bb[nt][1] = Vlo[n0*64 + (c1^sw)];
            }
#pragma unroll
            for (int nt = 0; nt < 8; nt++) mma16816(oacc[nt], ah, bb[nt]);
            // passes 2+3: P_lo * V_hi, P_hi * V_hi
#pragma unroll
            for (int nt = 0; nt < 8; nt++) {
                int n0 = nt*8 + qr;
                bb[nt][0] = Vhi[n0*64 + (c0^sw)];
                bb[nt][1] = Vhi[n0*64 + (c1^sw)];
            }
#pragma unroll
            for (int nt = 0; nt < 8; nt++) mma16816(oacc[nt], al, bb[nt]);
#pragma unroll
            for (int nt = 0; nt < 8; nt++) mma16816(oacc[nt], ah, bb[nt]);
        }
    }

    // ---- epilogue: normalize rows, write pre-split ctx ----
    const int b = bh >> 4, h = bh & 15;
    const float inv0 = 1.0f / lrow[0], inv1 = 1.0f / lrow[1];
    int q = q0 + wid*16 + qr;
#pragma unroll
    for (int nt = 0; nt < 8; nt++) {
        int du = h*32 + nt*4 + qc;    // u32 col in 512-wide row
        unsigned hi, lo;
        split2(oacc[nt][0]*inv0, oacc[nt][1]*inv0, hi, lo);
        g_ctxhi[(size_t)(b*Ldim + q)*512 + du] = hi;
        g_ctxlo[(size_t)(b*Ldim + q)*512 + du] = lo;
        split2(oacc[nt][2]*inv1, oacc[nt][3]*inv1, hi, lo);
        g_ctxhi[(size_t)(b*Ldim + q + 8)*512 + du] = hi;
        g_ctxlo[(size_t)(b*Ldim + q + 8)*512 + du] = lo;
    }
}

// ============================================================
extern "C" void kernel_launch(void* const* d_in, const int* in_sizes, int n_in,
                              void* d_out, int out_size)
{
    const float* x     = (const float*)d_in[0];
    const float* Wqkv  = (const float*)d_in[1];
    const float* qb    = (const float*)d_in[2];
    const float* vb    = (const float*)d_in[3];
    const float* sml   = (const float*)d_in[4];
    const float* Wproj = (const float*)d_in[5];
    const float* bproj = (const float*)d_in[6];
    float* out = (float*)d_out;

    unsigned *xhi, *xlo, *wqh, *wql, *wph, *wpl, *chi, *clo;
    cudaGetSymbolAddress((void**)&xhi, g_xhi);    cudaGetSymbolAddress((void**)&xlo, g_xlo);
    cudaGetSymbolAddress((void**)&wqh, g_wqkvhi); cudaGetSymbolAddress((void**)&wql, g_wqkvlo);
    cudaGetSymbolAddress((void**)&wph, g_wprohi); cudaGetSymbolAddress((void**)&wpl, g_wprolo);
    cudaGetSymbolAddress((void**)&chi, g_ctxhi);  cudaGetSymbolAddress((void**)&clo, g_ctxlo);

    const int GEMM_SMEM = 81920;   // 2 x 40KB stages -> 2 CTA/SM
    const int ATTN_SMEM = 98304;   // 96KB
    cudaFuncSetAttribute(gemm_ker<0>, cudaFuncAttributeMaxDynamicSharedMemorySize, GEMM_SMEM);
    cudaFuncSetAttribute(gemm_ker<1>, cudaFuncAttributeMaxDynamicSharedMemorySize, GEMM_SMEM);
    cudaFuncSetAttribute(attn_ker,    cudaFuncAttributeMaxDynamicSharedMemorySize, ATTN_SMEM);

    split_ker<<<(Mdim*Cdim/4)/256, 256>>>(x,     xhi, xlo, Mdim*Cdim/4);
    split_ker<<<(3*Cdim*Cdim/4)/256, 256>>>(Wqkv, wqh, wql, 3*Cdim*Cdim/4);
    split_ker<<<(Cdim*Cdim/4)/256, 256>>>(Wproj, wph, wpl, Cdim*Cdim/4);

    gemm_ker<0><<<dim3(3*Cdim/128, Mdim/128), 256, GEMM_SMEM>>>(
        xhi, xlo, wqh, wql, qb, vb, nullptr);

    norm_kernel<<<(2*BHL)/8, 256>>>(sml);

    attn_ker<<<dim3(Ldim/128, Bdim*Hdim), 256, ATTN_SMEM>>>();

    gemm_ker<1><<<dim3(Cdim/128, Mdim/128), 256, GEMM_SMEM>>>(
        chi, clo, wph, wpl, bproj, nullptr, out);
}

// round 15
// speedup vs baseline: 1.3587x; 1.3587x over previous
#include <cuda_runtime.h>
#include <cuda_fp16.h>
#include <math.h>

#define Bdim 4
#define Ldim 2048
#define Cdim 1024
#define Hdim 16
#define Mdim (Bdim*Ldim)          // 8192
#define MAX_SCALE_MUL 4.605170185988091f   // log(100)
#define BHL (Bdim*Hdim*Ldim)      // 131072

// ---- scratch (__device__ globals; allocation-free rule) ----
// packed fp16x2 operand arrays (u32 = one half2)
__device__ unsigned g_xhi   [Mdim*512],  g_xlo   [Mdim*512];   // x split (A of QKV)
__device__ unsigned g_wqkvhi[3072*512];                        // Wqkv hi only (B)
__device__ unsigned g_wprohi[1024*512];                        // Wproj hi only (B)
__device__ unsigned g_ctxhi [Mdim*512],  g_ctxlo [Mdim*512];   // ctx split (A of proj)
__device__ float g_q  [BHL*64];   // [b,h,l,d] fp32
__device__ float g_k  [BHL*64];
__device__ float g_vt [BHL*64];   // [b,h,d,l] fp32

// ============================================================
// helpers
// ============================================================
__device__ __forceinline__ void split2h(float x0, float x1, unsigned &hi, unsigned &lo) {
    __half2 h2 = __floats2half2_rn(x0, x1);
    float hx = __low2float(h2), hy = __high2float(h2);
    __half2 l2 = __floats2half2_rn(x0 - hx, x1 - hy);
    hi = *reinterpret_cast<unsigned*>(&h2);
    lo = *reinterpret_cast<unsigned*>(&l2);
}
__device__ __forceinline__ unsigned hi2h(float x0, float x1) {
    __half2 h2 = __floats2half2_rn(x0, x1);
    return *reinterpret_cast<unsigned*>(&h2);
}

// fp16 mma, non-volatile (pure function of inputs)
__device__ __forceinline__ void mmah(float* c, const unsigned* a, const unsigned* b) {
    asm("mma.sync.aligned.m16n8k16.row.col.f32.f16.f16.f32 "
        "{%0,%1,%2,%3},{%4,%5,%6,%7},{%8,%9},{%0,%1,%2,%3};\n"
        : "+f"(c[0]), "+f"(c[1]), "+f"(c[2]), "+f"(c[3])
        : "r"(a[0]), "r"(a[1]), "r"(a[2]), "r"(a[3]), "r"(b[0]), "r"(b[1]));
}

__device__ __forceinline__ void ldsm4(unsigned &d0, unsigned &d1, unsigned &d2, unsigned &d3,
                                      unsigned addr) {
    asm volatile("ldmatrix.sync.aligned.m8n8.x4.shared.b16 {%0,%1,%2,%3}, [%4];"
        : "=r"(d0), "=r"(d1), "=r"(d2), "=r"(d3) : "r"(addr));
}

__device__ __forceinline__ void cpa16(unsigned dst, const void* src) {
    asm volatile("cp.async.cg.shared.global [%0], [%1], 16;" :: "r"(dst), "l"(src) : "memory");
}
__device__ __forceinline__ void cpa_commit() { asm volatile("cp.async.commit_group;" ::: "memory"); }
__device__ __forceinline__ void cpa_wait0()  { asm volatile("cp.async.wait_group 0;" ::: "memory"); }
__device__ __forceinline__ void cpa_wait1()  { asm volatile("cp.async.wait_group 1;" ::: "memory"); }

// ============================================================
// elementwise fp32 -> fp16 split kernels
// ============================================================
__global__ __launch_bounds__(256) void split_ker(
    const float* __restrict__ src, unsigned* __restrict__ hi,
    unsigned* __restrict__ lo, int n4)
{
    int i = blockIdx.x * 256 + threadIdx.x;
    if (i < n4) {
        float4 v = ((const float4*)src)[i];
        unsigned h0,l0,h1,l1;
        split2h(v.x, v.y, h0, l0);
        split2h(v.z, v.w, h1, l1);
        ((uint2*)hi)[i] = make_uint2(h0, h1);
        ((uint2*)lo)[i] = make_uint2(l0, l1);
    }
}
__global__ __launch_bounds__(256) void splithi_ker(
    const float* __restrict__ src, unsigned* __restrict__ hi, int n4)
{
    int i = blockIdx.x * 256 + threadIdx.x;
    if (i < n4) {
        float4 v = ((const float4*)src)[i];
        ((uint2*)hi)[i] = make_uint2(hi2h(v.x, v.y), hi2h(v.z, v.w));
    }
}

// ============================================================
// GEMM: C[M,N] = A[M,1024].W[N,1024]^T, fp16 2-term (A split, B hi)
// CTA 128x128, BK=32, 2-stage cp.async, 8 warps (2M x 4N), 2 CTA/SM.
// Stage (30KB): Ahi@0 | Alo@10240 | Whi@20480
// Rows padded to 80B: ldmatrix conflict-free without swizzle.
// MMA stream = 2 passes x 16 independent accumulators.
// ============================================================
__device__ __forceinline__ void gemm_issue_tile(
    const unsigned* __restrict__ Ah, const unsigned* __restrict__ Al,
    const unsigned* __restrict__ Wh,
    int bm, int bn, int kt, unsigned sb, int tid)
{
    const int r  = tid >> 1;          // 0..127
    const int ku = kt * 16;           // u32 col offset (BK=32 = 16 u32)
    const unsigned* g0 = Ah + (size_t)(bm + r)*512 + ku;
    const unsigned* g1 = Al + (size_t)(bm + r)*512 + ku;
    const unsigned* g2 = Wh + (size_t)(bn + r)*512 + ku;
#pragma unroll
    for (int c = 0; c < 2; c++) {
        int cc = (tid & 1)*2 + c;     // chunk 0..3
        unsigned off = (unsigned)(r*80 + cc*16);
        cpa16(sb + off,          g0 + cc*4);
        cpa16(sb + 10240u + off, g1 + cc*4);
        cpa16(sb + 20480u + off, g2 + cc*4);
    }
}

template<int MODE>
__global__ __launch_bounds__(256, 2) void gemm_ker(
    const unsigned* __restrict__ Ahg, const unsigned* __restrict__ Alg,
    const unsigned* __restrict__ Whg,
    const float* __restrict__ bq, const float* __restrict__ bv,
    float* __restrict__ out)
{
    extern __shared__ unsigned smg[];
    const int tid  = threadIdx.x;
    const int lane = tid & 31;
    const int wid  = tid >> 5;
    const int wm   = wid >> 2, wn = wid & 3;
    const int qr   = lane >> 2, qc = lane & 3;
    const int j    = lane >> 3, rr = lane & 7;   // ldsm lane decomposition
    const int bm = blockIdx.y * 128, bn = blockIdx.x * 128;
    const unsigned smbase = (unsigned)__cvta_generic_to_shared(smg);

    unsigned a_off[4], b_off[2];
#pragma unroll
    for (int mt = 0; mt < 4; mt++)
        a_off[mt] = (unsigned)((wm*64 + mt*16 + ((j & 1) << 3) + rr) * 80 + (j >> 1)*16);
#pragma unroll
    for (int p = 0; p < 2; p++)
        b_off[p] = (unsigned)((wn*32 + p*16 + ((j >> 1) << 3) + rr) * 80 + (j & 1)*16);

    float acc[4][4][4];
#pragma unroll
    for (int i = 0; i < 4; i++)
#pragma unroll
        for (int jj = 0; jj < 4; jj++)
#pragma unroll
            for (int t = 0; t < 4; t++) acc[i][jj][t] = 0.f;

    gemm_issue_tile(Ahg, Alg, Whg, bm, bn, 0, smbase, tid);
    cpa_commit();

    for (int kt = 0; kt < 32; kt++) {
        if (kt + 1 < 32) {
            gemm_issue_tile(Ahg, Alg, Whg, bm, bn, kt + 1,
                            smbase + ((kt + 1) & 1) * 30720u, tid);
            cpa_commit();
            cpa_wait1();
        } else {
            cpa_wait0();
        }
        __syncthreads();

        const unsigned sA = smbase + (unsigned)(kt & 1) * 30720u;
        const unsigned sW = sA + 20480u;
#pragma unroll
        for (int ks = 0; ks < 2; ks++) {
            const unsigned ko = (unsigned)(ks * 32);
            unsigned ah[4][4], al[4][4], bh[4][2];
#pragma unroll
            for (int mt = 0; mt < 4; mt++) {
                ldsm4(ah[mt][0], ah[mt][1], ah[mt][2], ah[mt][3], sA + a_off[mt] + ko);
                ldsm4(al[mt][0], al[mt][1], al[mt][2], al[mt][3], sA + 10240u + a_off[mt] + ko);
            }
#pragma unroll
            for (int p = 0; p < 2; p++) {
                ldsm4(bh[2*p][0], bh[2*p][1], bh[2*p+1][0], bh[2*p+1][1], sW + b_off[p] + ko);
            }
            // 2 passes x 16 independent accumulators: acc += al*bh; acc += ah*bh
#pragma unroll
            for (int mt = 0; mt < 4; mt++)
#pragma unroll
                for (int nt = 0; nt < 4; nt++)
                    mmah(acc[mt][nt], al[mt], bh[nt]);
#pragma unroll
            for (int mt = 0; mt < 4; mt++)
#pragma unroll
                for (int nt = 0; nt < 4; nt++)
                    mmah(acc[mt][nt], ah[mt], bh[nt]);
        }
        __syncthreads();
    }

    if (MODE == 1) {
#pragma unroll
        for (int mt = 0; mt < 4; mt++)
#pragma unroll
            for (int nt = 0; nt < 4; nt++) {
                int m = bm + wm*64 + mt*16 + qr;
                int n = bn + wn*32 + nt*8 + qc*2;
                float b0 = bq[n], b1 = bq[n+1];
                *(float2*)(out + (size_t)m*Cdim + n)
                    = make_float2(acc[mt][nt][0] + b0, acc[mt][nt][1] + b1);
                *(float2*)(out + (size_t)(m+8)*Cdim + n)
                    = make_float2(acc[mt][nt][2] + b0, acc[mt][nt][3] + b1);
            }
    } else {
        const int which = bn >> 10;        // 0:q 1:k 2:v
        const int cb = bn & 1023;
#pragma unroll
        for (int mt = 0; mt < 4; mt++)
#pragma unroll
            for (int nt = 0; nt < 4; nt++) {
                int nloc = wn*32 + nt*8 + qc*2;
                int ncol = cb + nloc;
                int h = ncol >> 6, d = ncol & 63;
                float b0 = 0.f, b1 = 0.f;
                if (which == 0) { b0 = bq[ncol]; b1 = bq[ncol+1]; }
                if (which == 2) { b0 = bv[ncol]; b1 = bv[ncol+1]; }
#pragma unroll
                for (int hh = 0; hh < 2; hh++) {
                    int m = bm + wm*64 + mt*16 + qr + hh*8;
                    int b = m >> 11, l = m & (Ldim - 1);
                    float v0 = acc[mt][nt][hh*2]   + b0;
                    float v1 = acc[mt][nt][hh*2+1] + b1;
                    if (which == 2) {
                        size_t base = ((size_t)(b*Hdim + h)*64 + d)*Ldim + l;
                        g_vt[base]        = v0;
                        g_vt[base + Ldim] = v1;
                    } else {
                        float* dst = (which == 0) ? g_q : g_k;
                        *(float2*)(dst + ((size_t)(b*Hdim + h)*Ldim + l)*64 + d)
                            = make_float2(v0, v1);
                    }
                }
            }
    }
}

// ============================================================
// L2-normalize q,k rows (fp32 in place); q *= exp(min(sml[h],log100))
// ============================================================
__global__ __launch_bounds__(256) void norm_kernel(const float* __restrict__ sml)
{
    const int NR = BHL;
    int w = blockIdx.x * 8 + (threadIdx.x >> 5);
    int lane = threadIdx.x & 31;
    bool is_q = (w < NR);
    float* p = is_q ? g_q : g_k;
    int r = is_q ? w : (w - NR);
    float a0 = p[(size_t)r*64 + lane];
    float a1 = p[(size_t)r*64 + lane + 32];
    float s = a0*a0 + a1*a1;
#pragma unroll
    for (int off = 16; off > 0; off >>= 1)
        s += __shfl_xor_sync(0xffffffffu, s, off);
    float mul = 1.0f;
    if (is_q) {
        int h = (r >> 11) & (Hdim - 1);
        mul = __expf(fminf(sml[h], MAX_SCALE_MUL));
    }
    float inv = mul / fmaxf(sqrtf(s), 1e-12f);
    p[(size_t)r*64 + lane]      = a0 * inv;
    p[(size_t)r*64 + lane + 32] = a1 * inv;
}

// ============================================================
// attention tile loaders (fp32 -> fp16 -> swizzled smem)
// ============================================================
__device__ __forceinline__ void load_q_tile(
    const float* __restrict__ src, size_t row0,
    unsigned* __restrict__ Hi, unsigned* __restrict__ Lo, int tid)
{
#pragma unroll
    for (int p = 0; p < 8; p++) {
        int r = p*16 + (tid >> 4);
        int jj = tid & 15;
        const float4 v = *(const float4*)(src + (row0 + r)*64 + jj*4);
        unsigned h0,l0,h1,l1;
        split2h(v.x, v.y, h0, l0);
        split2h(v.z, v.w, h1, l1);
        int c = (2*jj) ^ ((r & 7) << 2);
        *(uint2*)&Hi[r*32 + c] = make_uint2(h0, h1);
        *(uint2*)&Lo[r*32 + c] = make_uint2(l0, l1);
    }
}

__device__ __forceinline__ void load_k_tile_hi(
    const float* __restrict__ src, size_t row0,
    unsigned* __restrict__ Hi, int tid)
{
#pragma unroll
    for (int p = 0; p < 8; p++) {
        int r = p*16 + (tid >> 4);
        int jj = tid & 15;
        const float4 v = *(const float4*)(src + (row0 + r)*64 + jj*4);
        int c = (2*jj) ^ ((r & 7) << 2);
        *(uint2*)&Hi[r*32 + c] = make_uint2(hi2h(v.x, v.y), hi2h(v.z, v.w));
    }
}

__device__ __forceinline__ void load_v_tile_hi(
    const float* __restrict__ Vg, int l0,
    unsigned* __restrict__ Hi, int tid)
{
#pragma unroll
    for (int p = 0; p < 8; p++) {
        int r = p*8 + (tid >> 5);
        int jj = tid & 31;
        const float4 v = *(const float4*)(Vg + (size_t)r*Ldim + l0 + jj*4);
        int c = (2*jj) ^ ((r & 7) << 2);
        *(uint2*)&Hi[r*64 + c] = make_uint2(hi2h(v.x, v.y), hi2h(v.z, v.w));
    }
}

// ============================================================
// Flash attention — fp16 2-term (Q,P split; K,V hi only).
// Block = (b,h) x 128-query tile, 8 warps, 64KB smem.
// smem u32: Qhi@0 Qlo@4096 Khi@8192 Vhi@12288
// ============================================================
__global__ __launch_bounds__(256) void attn_ker()
{
    extern __shared__ unsigned sma[];
    unsigned *Qhi = sma,         *Qlo = sma + 4096;
    unsigned *Khi = sma + 8192,  *Vhi = sma + 12288;

    const int tid = threadIdx.x, lane = tid & 31, wid = tid >> 5;
    const int qr = lane >> 2, qc = lane & 3;
    const int bh = blockIdx.y, q0 = blockIdx.x * 128;
    const float* Qg = g_q  + (size_t)bh * Ldim * 64;
    const float* Kg = g_k  + (size_t)bh * Ldim * 64;
    const float* Vg = g_vt + (size_t)bh * 64 * Ldim;

    load_q_tile(Qg, q0, Qhi, Qlo, tid);

    float oacc[8][4];
#pragma unroll
    for (int i = 0; i < 8; i++)
#pragma unroll
        for (int t = 0; t < 4; t++) oacc[i][t] = 0.f;
    float mrow[2] = {-1e30f, -1e30f}, lrow[2] = {0.f, 0.f};

    for (int kt = 0; kt < Ldim/128; kt++) {
        __syncthreads();
        load_k_tile_hi(Kg, (size_t)kt*128, Khi, tid);
        load_v_tile_hi(Vg, kt*128, Vhi, tid);
        __syncthreads();

        // ---- S = Q . K^T  (16 q rows x 128 keys per warp) ----
        float sacc[16][4];
#pragma unroll
        for (int i = 0; i < 16; i++)
#pragma unroll
            for (int t = 0; t < 4; t++) sacc[i][t] = 0.f;
#pragma unroll
        for (int ks = 0; ks < 4; ks++) {
            const int c0 = ks*8 + qc, c1 = c0 + 4, sw = qr << 2;
            int r0 = wid*16 + qr, r1 = r0 + 8;
            int i0 = r0*32 + (c0^sw), i1 = r1*32 + (c0^sw);
            int i2 = r0*32 + (c1^sw), i3 = r1*32 + (c1^sw);
            unsigned ah[4] = {Qhi[i0], Qhi[i1], Qhi[i2], Qhi[i3]};
            unsigned al[4] = {Qlo[i0], Qlo[i1], Qlo[i2], Qlo[i3]};
#pragma unroll
            for (int g = 0; g < 2; g++) {
                unsigned bb[8][2];
#pragma unroll
                for (int t = 0; t < 8; t++) {
                    int n0 = (g*8 + t)*8 + qr;
                    bb[t][0] = Khi[n0*32 + (c0^sw)];
                    bb[t][1] = Khi[n0*32 + (c1^sw)];
                }
#pragma unroll
                for (int t = 0; t < 8; t++) mmah(sacc[g*8+t], al, bb[t]);
#pragma unroll
                for (int t = 0; t < 8; t++) mmah(sacc[g*8+t], ah, bb[t]);
            }
        }

        // ---- online softmax (quad reduce) ----
#pragma unroll
        for (int hh = 0; hh < 2; hh++) {
            float mx = -1e30f;
#pragma unroll
            for (int nt = 0; nt < 16; nt++)
                mx = fmaxf(mx, fmaxf(sacc[nt][hh*2], sacc[nt][hh*2+1]));
            mx = fmaxf(mx, __shfl_xor_sync(0xffffffffu, mx, 1));
            mx = fmaxf(mx, __shfl_xor_sync(0xffffffffu, mx, 2));
            float mnew = fmaxf(mrow[hh], mx);
            float corr = __expf(mrow[hh] - mnew);
            float rs = 0.f;
#pragma unroll
            for (int nt = 0; nt < 16; nt++) {
                float e0 = __expf(sacc[nt][hh*2]   - mnew);
                float e1 = __expf(sacc[nt][hh*2+1] - mnew);
                sacc[nt][hh*2] = e0; sacc[nt][hh*2+1] = e1;
                rs += e0 + e1;
            }
            rs += __shfl_xor_sync(0xffffffffu, rs, 1);
            rs += __shfl_xor_sync(0xffffffffu, rs, 2);
            mrow[hh] = mnew;
            lrow[hh] = lrow[hh]*corr + rs;
#pragma unroll
            for (int nt = 0; nt < 8; nt++) {
                oacc[nt][hh*2]   *= corr;
                oacc[nt][hh*2+1] *= corr;
            }
        }

        // ---- O += P . V  (P split from sacc regs; V hi only) ----
#pragma unroll
        for (int ks = 0; ks < 8; ks++) {
            unsigned ah[4], al[4];
            split2h(sacc[2*ks][0],   sacc[2*ks][1],   ah[0], al[0]);
            split2h(sacc[2*ks][2],   sacc[2*ks][3],   ah[1], al[1]);
            split2h(sacc[2*ks+1][0], sacc[2*ks+1][1], ah[2], al[2]);
            split2h(sacc[2*ks+1][2], sacc[2*ks+1][3], ah[3], al[3]);
            const int c0 = ks*8 + qc, c1 = c0 + 4, sw = qr << 2;
            unsigned bb[8][2];
#pragma unroll
            for (int nt = 0; nt < 8; nt++) {
                int n0 = nt*8 + qr;
                bb[nt][0] = Vhi[n0*64 + (c0^sw)];
                bb[nt][1] = Vhi[n0*64 + (c1^sw)];
            }
#pragma unroll
            for (int nt = 0; nt < 8; nt++) mmah(oacc[nt], al, bb[nt]);
#pragma unroll
            for (int nt = 0; nt < 8; nt++) mmah(oacc[nt], ah, bb[nt]);
        }
    }

    // ---- epilogue: normalize rows, write pre-split ctx (fp16 hi/lo) ----
    const int b = bh >> 4, h = bh & 15;
    const float inv0 = 1.0f / lrow[0], inv1 = 1.0f / lrow[1];
    int q = q0 + wid*16 + qr;
#pragma unroll
    for (int nt = 0; nt < 8; nt++) {
        int du = h*32 + nt*4 + qc;    // u32 col in 512-wide row
        unsigned hi, lo;
        split2h(oacc[nt][0]*inv0, oacc[nt][1]*inv0, hi, lo);
        g_ctxhi[(size_t)(b*Ldim + q)*512 + du] = hi;
        g_ctxlo[(size_t)(b*Ldim + q)*512 + du] = lo;
        split2h(oacc[nt][2]*inv1, oacc[nt][3]*inv1, hi, lo);
        g_ctxhi[(size_t)(b*Ldim + q + 8)*512 + du] = hi;
        g_ctxlo[(size_t)(b*Ldim + q + 8)*512 + du] = lo;
    }
}

// ============================================================
extern "C" void kernel_launch(void* const* d_in, const int* in_sizes, int n_in,
                              void* d_out, int out_size)
{
    const float* x     = (const float*)d_in[0];
    const float* Wqkv  = (const float*)d_in[1];
    const float* qb    = (const float*)d_in[2];
    const float* vb    = (const float*)d_in[3];
    const float* sml   = (const float*)d_in[4];
    const float* Wproj = (const float*)d_in[5];
    const float* bproj = (const float*)d_in[6];
    float* out = (float*)d_out;

    unsigned *xhi, *xlo, *wqh, *wph, *chi, *clo;
    cudaGetSymbolAddress((void**)&xhi, g_xhi);    cudaGetSymbolAddress((void**)&xlo, g_xlo);
    cudaGetSymbolAddress((void**)&wqh, g_wqkvhi);
    cudaGetSymbolAddress((void**)&wph, g_wprohi);
    cudaGetSymbolAddress((void**)&chi, g_ctxhi);  cudaGetSymbolAddress((void**)&clo, g_ctxlo);

    const int GEMM_SMEM = 61440;   // 2 x 30KB stages -> 2 CTA/SM
    const int ATTN_SMEM = 65536;   // 64KB
    cudaFuncSetAttribute(gemm_ker<0>, cudaFuncAttributeMaxDynamicSharedMemorySize, GEMM_SMEM);
    cudaFuncSetAttribute(gemm_ker<1>, cudaFuncAttributeMaxDynamicSharedMemorySize, GEMM_SMEM);
    cudaFuncSetAttribute(attn_ker,    cudaFuncAttributeMaxDynamicSharedMemorySize, ATTN_SMEM);

    split_ker<<<(Mdim*Cdim/4)/256, 256>>>(x, xhi, xlo, Mdim*Cdim/4);
    splithi_ker<<<(3*Cdim*Cdim/4)/256, 256>>>(Wqkv,  wqh, 3*Cdim*Cdim/4);
    splithi_ker<<<(Cdim*Cdim/4)/256, 256>>>(Wproj, wph, Cdim*Cdim/4);

    gemm_ker<0><<<dim3(3*Cdim/128, Mdim/128), 256, GEMM_SMEM>>>(
        xhi, xlo, wqh, qb, vb, nullptr);

    norm_kernel<<<(2*BHL)/8, 256>>>(sml);

    attn_ker<<<dim3(Ldim/128, Bdim*Hdim), 256, ATTN_SMEM>>>();

    gemm_ker<1><<<dim3(Cdim/128, Mdim/128), 256, GEMM_SMEM>>>(
        chi, clo, wph, bproj, nullptr, out);
}

// round 16
// speedup vs baseline: 1.4633x; 1.0770x over previous
#include <cuda_runtime.h>
#include <cuda_fp16.h>
#include <math.h>

#define Bdim 4
#define Ldim 2048
#define Cdim 1024
#define Hdim 16
#define Mdim (Bdim*Ldim)          // 8192
#define MAX_SCALE_MUL 4.605170185988091f   // log(100)
#define BHL (Bdim*Hdim*Ldim)      // 131072

// ---- scratch (__device__ globals; allocation-free rule) ----
// packed fp16x2 operand arrays (u32 = one half2)
__device__ unsigned g_xhi   [Mdim*512],  g_xlo   [Mdim*512];   // x split (A of QKV)
__device__ unsigned g_wqkvhi[3072*512];                        // Wqkv hi only (B)
__device__ unsigned g_wprohi[1024*512];                        // Wproj hi only (B)
__device__ unsigned g_ctxhi [Mdim*512],  g_ctxlo [Mdim*512];   // ctx split (A of proj)
__device__ float g_q  [BHL*64];   // [b,h,l,d] fp32
__device__ float g_k  [BHL*64];
__device__ float g_vt [BHL*64];   // [b,h,d,l] fp32

// ============================================================
// helpers
// ============================================================
__device__ __forceinline__ void split2h(float x0, float x1, unsigned &hi, unsigned &lo) {
    __half2 h2 = __floats2half2_rn(x0, x1);
    float hx = __low2float(h2), hy = __high2float(h2);
    __half2 l2 = __floats2half2_rn(x0 - hx, x1 - hy);
    hi = *reinterpret_cast<unsigned*>(&h2);
    lo = *reinterpret_cast<unsigned*>(&l2);
}
__device__ __forceinline__ unsigned hi2h(float x0, float x1) {
    __half2 h2 = __floats2half2_rn(x0, x1);
    return *reinterpret_cast<unsigned*>(&h2);
}

// fp16 mma, non-volatile (pure function of inputs)
__device__ __forceinline__ void mmah(float* c, const unsigned* a, const unsigned* b) {
    asm("mma.sync.aligned.m16n8k16.row.col.f32.f16.f16.f32 "
        "{%0,%1,%2,%3},{%4,%5,%6,%7},{%8,%9},{%0,%1,%2,%3};\n"
        : "+f"(c[0]), "+f"(c[1]), "+f"(c[2]), "+f"(c[3])
        : "r"(a[0]), "r"(a[1]), "r"(a[2]), "r"(a[3]), "r"(b[0]), "r"(b[1]));
}

__device__ __forceinline__ void ldsm4(unsigned &d0, unsigned &d1, unsigned &d2, unsigned &d3,
                                      unsigned addr) {
    asm volatile("ldmatrix.sync.aligned.m8n8.x4.shared.b16 {%0,%1,%2,%3}, [%4];"
        : "=r"(d0), "=r"(d1), "=r"(d2), "=r"(d3) : "r"(addr));
}

__device__ __forceinline__ void cpa16(unsigned dst, const void* src) {
    asm volatile("cp.async.cg.shared.global [%0], [%1], 16;" :: "r"(dst), "l"(src) : "memory");
}
__device__ __forceinline__ void cpa_commit() { asm volatile("cp.async.commit_group;" ::: "memory"); }
__device__ __forceinline__ void cpa_wait0()  { asm volatile("cp.async.wait_group 0;" ::: "memory"); }
__device__ __forceinline__ void cpa_wait1()  { asm volatile("cp.async.wait_group 1;" ::: "memory"); }

// ============================================================
// elementwise fp32 -> fp16 split kernels
// ============================================================
__global__ __launch_bounds__(256) void split_ker(
    const float* __restrict__ src, unsigned* __restrict__ hi,
    unsigned* __restrict__ lo, int n4)
{
    int i = blockIdx.x * 256 + threadIdx.x;
    if (i < n4) {
        float4 v = ((const float4*)src)[i];
        unsigned h0,l0,h1,l1;
        split2h(v.x, v.y, h0, l0);
        split2h(v.z, v.w, h1, l1);
        ((uint2*)hi)[i] = make_uint2(h0, h1);
        ((uint2*)lo)[i] = make_uint2(l0, l1);
    }
}
__global__ __launch_bounds__(256) void splithi_ker(
    const float* __restrict__ src, unsigned* __restrict__ hi, int n4)
{
    int i = blockIdx.x * 256 + threadIdx.x;
    if (i < n4) {
        float4 v = ((const float4*)src)[i];
        ((uint2*)hi)[i] = make_uint2(hi2h(v.x, v.y), hi2h(v.z, v.w));
    }
}

// ============================================================
// GEMM: C[M,N] = A[M,1024].W[N,1024]^T, fp16 2-term (A split, B hi)
// CTA 128x128, BK=32, 2-stage cp.async, 8 warps (2M x 4N), 2 CTA/SM.
// Stage (30KB): Ahi@0 | Alo@10240 | Whi@20480
// Rows padded to 80B: ldmatrix conflict-free without swizzle.
// ============================================================
__device__ __forceinline__ void gemm_issue_tile(
    const unsigned* __restrict__ Ah, const unsigned* __restrict__ Al,
    const unsigned* __restrict__ Wh,
    int bm, int bn, int kt, unsigned sb, int tid)
{
    const int r  = tid >> 1;          // 0..127
    const int ku = kt * 16;           // u32 col offset (BK=32 = 16 u32)
    const unsigned* g0 = Ah + (size_t)(bm + r)*512 + ku;
    const unsigned* g1 = Al + (size_t)(bm + r)*512 + ku;
    const unsigned* g2 = Wh + (size_t)(bn + r)*512 + ku;
#pragma unroll
    for (int c = 0; c < 2; c++) {
        int cc = (tid & 1)*2 + c;     // chunk 0..3
        unsigned off = (unsigned)(r*80 + cc*16);
        cpa16(sb + off,          g0 + cc*4);
        cpa16(sb + 10240u + off, g1 + cc*4);
        cpa16(sb + 20480u + off, g2 + cc*4);
    }
}

template<int MODE>
__global__ __launch_bounds__(256, 2) void gemm_ker(
    const unsigned* __restrict__ Ahg, const unsigned* __restrict__ Alg,
    const unsigned* __restrict__ Whg,
    const float* __restrict__ bq, const float* __restrict__ bv,
    float* __restrict__ out)
{
    extern __shared__ unsigned smg[];
    const int tid  = threadIdx.x;
    const int lane = tid & 31;
    const int wid  = tid >> 5;
    const int wm   = wid >> 2, wn = wid & 3;
    const int qr   = lane >> 2, qc = lane & 3;
    const int j    = lane >> 3, rr = lane & 7;   // ldsm lane decomposition
    const int bm = blockIdx.y * 128, bn = blockIdx.x * 128;
    const unsigned smbase = (unsigned)__cvta_generic_to_shared(smg);

    unsigned a_off[4], b_off[2];
#pragma unroll
    for (int mt = 0; mt < 4; mt++)
        a_off[mt] = (unsigned)((wm*64 + mt*16 + ((j & 1) << 3) + rr) * 80 + (j >> 1)*16);
#pragma unroll
    for (int p = 0; p < 2; p++)
        b_off[p] = (unsigned)((wn*32 + p*16 + ((j >> 1) << 3) + rr) * 80 + (j & 1)*16);

    float acc[4][4][4];
#pragma unroll
    for (int i = 0; i < 4; i++)
#pragma unroll
        for (int jj = 0; jj < 4; jj++)
#pragma unroll
            for (int t = 0; t < 4; t++) acc[i][jj][t] = 0.f;

    gemm_issue_tile(Ahg, Alg, Whg, bm, bn, 0, smbase, tid);
    cpa_commit();

    for (int kt = 0; kt < 32; kt++) {
        if (kt + 1 < 32) {
            gemm_issue_tile(Ahg, Alg, Whg, bm, bn, kt + 1,
                            smbase + ((kt + 1) & 1) * 30720u, tid);
            cpa_commit();
            cpa_wait1();
        } else {
            cpa_wait0();
        }
        __syncthreads();

        const unsigned sA = smbase + (unsigned)(kt & 1) * 30720u;
        const unsigned sW = sA + 20480u;
#pragma unroll
        for (int ks = 0; ks < 2; ks++) {
            const unsigned ko = (unsigned)(ks * 32);
            unsigned ah[4][4], al[4][4], bh[4][2];
#pragma unroll
            for (int mt = 0; mt < 4; mt++) {
                ldsm4(ah[mt][0], ah[mt][1], ah[mt][2], ah[mt][3], sA + a_off[mt] + ko);
                ldsm4(al[mt][0], al[mt][1], al[mt][2], al[mt][3], sA + 10240u + a_off[mt] + ko);
            }
#pragma unroll
            for (int p = 0; p < 2; p++) {
                ldsm4(bh[2*p][0], bh[2*p][1], bh[2*p+1][0], bh[2*p+1][1], sW + b_off[p] + ko);
            }
            // 2 passes x 16 independent accumulators: acc += al*bh; acc += ah*bh
#pragma unroll
            for (int mt = 0; mt < 4; mt++)
#pragma unroll
                for (int nt = 0; nt < 4; nt++)
                    mmah(acc[mt][nt], al[mt], bh[nt]);
#pragma unroll
            for (int mt = 0; mt < 4; mt++)
#pragma unroll
                for (int nt = 0; nt < 4; nt++)
                    mmah(acc[mt][nt], ah[mt], bh[nt]);
        }
        __syncthreads();
    }

    if (MODE == 1) {
#pragma unroll
        for (int mt = 0; mt < 4; mt++)
#pragma unroll
            for (int nt = 0; nt < 4; nt++) {
                int m = bm + wm*64 + mt*16 + qr;
                int n = bn + wn*32 + nt*8 + qc*2;
                float b0 = bq[n], b1 = bq[n+1];
                *(float2*)(out + (size_t)m*Cdim + n)
                    = make_float2(acc[mt][nt][0] + b0, acc[mt][nt][1] + b1);
                *(float2*)(out + (size_t)(m+8)*Cdim + n)
                    = make_float2(acc[mt][nt][2] + b0, acc[mt][nt][3] + b1);
            }
    } else {
        const int which = bn >> 10;        // 0:q 1:k 2:v
        const int cb = bn & 1023;
#pragma unroll
        for (int mt = 0; mt < 4; mt++)
#pragma unroll
            for (int nt = 0; nt < 4; nt++) {
                int nloc = wn*32 + nt*8 + qc*2;
                int ncol = cb + nloc;
                int h = ncol >> 6, d = ncol & 63;
                float b0 = 0.f, b1 = 0.f;
                if (which == 0) { b0 = bq[ncol]; b1 = bq[ncol+1]; }
                if (which == 2) { b0 = bv[ncol]; b1 = bv[ncol+1]; }
#pragma unroll
                for (int hh = 0; hh < 2; hh++) {
                    int m = bm + wm*64 + mt*16 + qr + hh*8;
                    int b = m >> 11, l = m & (Ldim - 1);
                    float v0 = acc[mt][nt][hh*2]   + b0;
                    float v1 = acc[mt][nt][hh*2+1] + b1;
                    if (which == 2) {
                        size_t base = ((size_t)(b*Hdim + h)*64 + d)*Ldim + l;
                        g_vt[base]        = v0;
                        g_vt[base + Ldim] = v1;
                    } else {
                        float* dst = (which == 0) ? g_q : g_k;
                        *(float2*)(dst + ((size_t)(b*Hdim + h)*Ldim + l)*64 + d)
                            = make_float2(v0, v1);
                    }
                }
            }
    }
}

// ============================================================
// L2-normalize q,k rows (fp32 in place); q *= exp(min(sml[h],log100))
// ============================================================
__global__ __launch_bounds__(256) void norm_kernel(const float* __restrict__ sml)
{
    const int NR = BHL;
    int w = blockIdx.x * 8 + (threadIdx.x >> 5);
    int lane = threadIdx.x & 31;
    bool is_q = (w < NR);
    float* p = is_q ? g_q : g_k;
    int r = is_q ? w : (w - NR);
    float a0 = p[(size_t)r*64 + lane];
    float a1 = p[(size_t)r*64 + lane + 32];
    float s = a0*a0 + a1*a1;
#pragma unroll
    for (int off = 16; off > 0; off >>= 1)
        s += __shfl_xor_sync(0xffffffffu, s, off);
    float mul = 1.0f;
    if (is_q) {
        int h = (r >> 11) & (Hdim - 1);
        mul = __expf(fminf(sml[h], MAX_SCALE_MUL));
    }
    float inv = mul / fmaxf(sqrtf(s), 1e-12f);
    p[(size_t)r*64 + lane]      = a0 * inv;
    p[(size_t)r*64 + lane + 32] = a1 * inv;
}

// ============================================================
// attention tile loaders (fp32 -> fp16 hi -> swizzled smem)
// ============================================================
__device__ __forceinline__ void load_tile_hi_128x64(
    const float* __restrict__ src, size_t row0,
    unsigned* __restrict__ Hi, int tid)
{
#pragma unroll
    for (int p = 0; p < 8; p++) {
        int r = p*16 + (tid >> 4);
        int jj = tid & 15;
        const float4 v = *(const float4*)(src + (row0 + r)*64 + jj*4);
        int c = (2*jj) ^ ((r & 7) << 2);
        *(uint2*)&Hi[r*32 + c] = make_uint2(hi2h(v.x, v.y), hi2h(v.z, v.w));
    }
}

__device__ __forceinline__ void load_v_tile_hi(
    const float* __restrict__ Vg, int l0,
    unsigned* __restrict__ Hi, int tid)
{
#pragma unroll
    for (int p = 0; p < 8; p++) {
        int r = p*8 + (tid >> 5);
        int jj = tid & 31;
        const float4 v = *(const float4*)(Vg + (size_t)r*Ldim + l0 + jj*4);
        int c = (2*jj) ^ ((r & 7) << 2);
        *(uint2*)&Hi[r*64 + c] = make_uint2(hi2h(v.x, v.y), hi2h(v.z, v.w));
    }
}

// ============================================================
// Flash attention — S pass 1-term (Q,K fp16 hi); PV 2-term
// (P split, V hi). Block = (b,h) x 128-query tile, 8 warps, 48KB smem.
// smem u32: Qhi@0 Khi@4096 Vhi@8192
// ============================================================
__global__ __launch_bounds__(256) void attn_ker()
{
    extern __shared__ unsigned sma[];
    unsigned *Qhi = sma, *Khi = sma + 4096, *Vhi = sma + 8192;

    const int tid = threadIdx.x, lane = tid & 31, wid = tid >> 5;
    const int qr = lane >> 2, qc = lane & 3;
    const int bh = blockIdx.y, q0 = blockIdx.x * 128;
    const float* Qg = g_q  + (size_t)bh * Ldim * 64;
    const float* Kg = g_k  + (size_t)bh * Ldim * 64;
    const float* Vg = g_vt + (size_t)bh * 64 * Ldim;

    load_tile_hi_128x64(Qg, q0, Qhi, tid);

    float oacc[8][4];
#pragma unroll
    for (int i = 0; i < 8; i++)
#pragma unroll
        for (int t = 0; t < 4; t++) oacc[i][t] = 0.f;
    float mrow[2] = {-1e30f, -1e30f}, lrow[2] = {0.f, 0.f};

    for (int kt = 0; kt < Ldim/128; kt++) {
        __syncthreads();
        load_tile_hi_128x64(Kg, (size_t)kt*128, Khi, tid);
        load_v_tile_hi(Vg, kt*128, Vhi, tid);
        __syncthreads();

        // ---- S = Q . K^T  (1-term: qh * kh) ----
        float sacc[16][4];
#pragma unroll
        for (int i = 0; i < 16; i++)
#pragma unroll
            for (int t = 0; t < 4; t++) sacc[i][t] = 0.f;
#pragma unroll
        for (int ks = 0; ks < 4; ks++) {
            const int c0 = ks*8 + qc, c1 = c0 + 4, sw = qr << 2;
            int r0 = wid*16 + qr, r1 = r0 + 8;
            int i0 = r0*32 + (c0^sw), i1 = r1*32 + (c0^sw);
            int i2 = r0*32 + (c1^sw), i3 = r1*32 + (c1^sw);
            unsigned ah[4] = {Qhi[i0], Qhi[i1], Qhi[i2], Qhi[i3]};
#pragma unroll
            for (int g = 0; g < 2; g++) {
                unsigned bb[8][2];
#pragma unroll
                for (int t = 0; t < 8; t++) {
                    int n0 = (g*8 + t)*8 + qr;
                    bb[t][0] = Khi[n0*32 + (c0^sw)];
                    bb[t][1] = Khi[n0*32 + (c1^sw)];
                }
#pragma unroll
                for (int t = 0; t < 8; t++) mmah(sacc[g*8+t], ah, bb[t]);
            }
        }

        // ---- online softmax (quad reduce) ----
#pragma unroll
        for (int hh = 0; hh < 2; hh++) {
            float mx = -1e30f;
#pragma unroll
            for (int nt = 0; nt < 16; nt++)
                mx = fmaxf(mx, fmaxf(sacc[nt][hh*2], sacc[nt][hh*2+1]));
            mx = fmaxf(mx, __shfl_xor_sync(0xffffffffu, mx, 1));
            mx = fmaxf(mx, __shfl_xor_sync(0xffffffffu, mx, 2));
            float mnew = fmaxf(mrow[hh], mx);
            float corr = __expf(mrow[hh] - mnew);
            float rs = 0.f;
#pragma unroll
            for (int nt = 0; nt < 16; nt++) {
                float e0 = __expf(sacc[nt][hh*2]   - mnew);
                float e1 = __expf(sacc[nt][hh*2+1] - mnew);
                sacc[nt][hh*2] = e0; sacc[nt][hh*2+1] = e1;
                rs += e0 + e1;
            }
            rs += __shfl_xor_sync(0xffffffffu, rs, 1);
            rs += __shfl_xor_sync(0xffffffffu, rs, 2);
            mrow[hh] = mnew;
            lrow[hh] = lrow[hh]*corr + rs;
#pragma unroll
            for (int nt = 0; nt < 8; nt++) {
                oacc[nt][hh*2]   *= corr;
                oacc[nt][hh*2+1] *= corr;
            }
        }

        // ---- O += P . V  (P split from sacc regs; V hi only) ----
#pragma unroll
        for (int ks = 0; ks < 8; ks++) {
            unsigned ah[4], al[4];
            split2h(sacc[2*ks][0],   sacc[2*ks][1],   ah[0], al[0]);
            split2h(sacc[2*ks][2],   sacc[2*ks][3],   ah[1], al[1]);
            split2h(sacc[2*ks+1][0], sacc[2*ks+1][1], ah[2], al[2]);
            split2h(sacc[2*ks+1][2], sacc[2*ks+1][3], ah[3], al[3]);
            const int c0 = ks*8 + qc, c1 = c0 + 4, sw = qr << 2;
            unsigned bb[8][2];
#pragma unroll
            for (int nt = 0; nt < 8; nt++) {
                int n0 = nt*8 + qr;
                bb[nt][0] = Vhi[n0*64 + (c0^sw)];
                bb[nt][1] = Vhi[n0*64 + (c1^sw)];
            }
#pragma unroll
            for (int nt = 0; nt < 8; nt++) mmah(oacc[nt], al, bb[nt]);
#pragma unroll
            for (int nt = 0; nt < 8; nt++) mmah(oacc[nt], ah, bb[nt]);
        }
    }

    // ---- epilogue: normalize rows, write pre-split ctx (fp16 hi/lo) ----
    const int b = bh >> 4, h = bh & 15;
    const float inv0 = 1.0f / lrow[0], inv1 = 1.0f / lrow[1];
    int q = q0 + wid*16 + qr;
#pragma unroll
    for (int nt = 0; nt < 8; nt++) {
        int du = h*32 + nt*4 + qc;    // u32 col in 512-wide row
        unsigned hi, lo;
        split2h(oacc[nt][0]*inv0, oacc[nt][1]*inv0, hi, lo);
        g_ctxhi[(size_t)(b*Ldim + q)*512 + du] = hi;
        g_ctxlo[(size_t)(b*Ldim + q)*512 + du] = lo;
        split2h(oacc[nt][2]*inv1, oacc[nt][3]*inv1, hi, lo);
        g_ctxhi[(size_t)(b*Ldim + q + 8)*512 + du] = hi;
        g_ctxlo[(size_t)(b*Ldim + q + 8)*512 + du] = lo;
    }
}

// ============================================================
extern "C" void kernel_launch(void* const* d_in, const int* in_sizes, int n_in,
                              void* d_out, int out_size)
{
    const float* x     = (const float*)d_in[0];
    const float* Wqkv  = (const float*)d_in[1];
    const float* qb    = (const float*)d_in[2];
    const float* vb    = (const float*)d_in[3];
    const float* sml   = (const float*)d_in[4];
    const float* Wproj = (const float*)d_in[5];
    const float* bproj = (const float*)d_in[6];
    float* out = (float*)d_out;

    unsigned *xhi, *xlo, *wqh, *wph, *chi, *clo;
    cudaGetSymbolAddress((void**)&xhi, g_xhi);    cudaGetSymbolAddress((void**)&xlo, g_xlo);
    cudaGetSymbolAddress((void**)&wqh, g_wqkvhi);
    cudaGetSymbolAddress((void**)&wph, g_wprohi);
    cudaGetSymbolAddress((void**)&chi, g_ctxhi);  cudaGetSymbolAddress((void**)&clo, g_ctxlo);

    const int GEMM_SMEM = 61440;   // 2 x 30KB stages -> 2 CTA/SM
    const int ATTN_SMEM = 49152;   // 48KB
    cudaFuncSetAttribute(gemm_ker<0>, cudaFuncAttributeMaxDynamicSharedMemorySize, GEMM_SMEM);
    cudaFuncSetAttribute(gemm_ker<1>, cudaFuncAttributeMaxDynamicSharedMemorySize, GEMM_SMEM);
    cudaFuncSetAttribute(attn_ker,    cudaFuncAttributeMaxDynamicSharedMemorySize, ATTN_SMEM);

    split_ker<<<(Mdim*Cdim/4)/256, 256>>>(x, xhi, xlo, Mdim*Cdim/4);
    splithi_ker<<<(3*Cdim*Cdim/4)/256, 256>>>(Wqkv,  wqh, 3*Cdim*Cdim/4);
    splithi_ker<<<(Cdim*Cdim/4)/256, 256>>>(Wproj, wph, Cdim*Cdim/4);

    gemm_ker<0><<<dim3(3*Cdim/128, Mdim/128), 256, GEMM_SMEM>>>(
        xhi, xlo, wqh, qb, vb, nullptr);

    norm_kernel<<<(2*BHL)/8, 256>>>(sml);

    attn_ker<<<dim3(Ldim/128, Bdim*Hdim), 256, ATTN_SMEM>>>();

    gemm_ker<1><<<dim3(Cdim/128, Mdim/128), 256, GEMM_SMEM>>>(
        chi, clo, wph, bproj, nullptr, out);
}

// round 17
// speedup vs baseline: 1.8075x; 1.2352x over previous
#include <cuda_runtime.h>
#include <cuda_fp16.h>
#include <math.h>

#define Bdim 4
#define Ldim 2048
#define Cdim 1024
#define Hdim 16
#define Mdim (Bdim*Ldim)          // 8192
#define MAX_SCALE_MUL 4.605170185988091f   // log(100)
#define BHL (Bdim*Hdim*Ldim)      // 131072

// ---- scratch (__device__ globals; allocation-free rule) ----
// packed fp16x2 operand arrays (u32 = one half2)
__device__ unsigned g_xhi   [Mdim*512];    // x fp16 (A of QKV)
__device__ unsigned g_wqkvhi[3072*512];    // Wqkv fp16 (B)
__device__ unsigned g_wprohi[1024*512];    // Wproj fp16 (B)
__device__ unsigned g_ctxhi [Mdim*512];    // ctx fp16 (A of proj)
__device__ float g_q  [BHL*64];   // [b,h,l,d] fp32
__device__ float g_k  [BHL*64];
__device__ float g_vt [BHL*64];   // [b,h,d,l] fp32

// ============================================================
// helpers
// ============================================================
__device__ __forceinline__ void split2h(float x0, float x1, unsigned &hi, unsigned &lo) {
    __half2 h2 = __floats2half2_rn(x0, x1);
    float hx = __low2float(h2), hy = __high2float(h2);
    __half2 l2 = __floats2half2_rn(x0 - hx, x1 - hy);
    hi = *reinterpret_cast<unsigned*>(&h2);
    lo = *reinterpret_cast<unsigned*>(&l2);
}
__device__ __forceinline__ unsigned hi2h(float x0, float x1) {
    __half2 h2 = __floats2half2_rn(x0, x1);
    return *reinterpret_cast<unsigned*>(&h2);
}

// fp16 mma, non-volatile (pure function of inputs)
__device__ __forceinline__ void mmah(float* c, const unsigned* a, const unsigned* b) {
    asm("mma.sync.aligned.m16n8k16.row.col.f32.f16.f16.f32 "
        "{%0,%1,%2,%3},{%4,%5,%6,%7},{%8,%9},{%0,%1,%2,%3};\n"
        : "+f"(c[0]), "+f"(c[1]), "+f"(c[2]), "+f"(c[3])
        : "r"(a[0]), "r"(a[1]), "r"(a[2]), "r"(a[3]), "r"(b[0]), "r"(b[1]));
}

__device__ __forceinline__ void ldsm4(unsigned &d0, unsigned &d1, unsigned &d2, unsigned &d3,
                                      unsigned addr) {
    asm volatile("ldmatrix.sync.aligned.m8n8.x4.shared.b16 {%0,%1,%2,%3}, [%4];"
        : "=r"(d0), "=r"(d1), "=r"(d2), "=r"(d3) : "r"(addr));
}

__device__ __forceinline__ void cpa16(unsigned dst, const void* src) {
    asm volatile("cp.async.cg.shared.global [%0], [%1], 16;" :: "r"(dst), "l"(src) : "memory");
}
__device__ __forceinline__ void cpa_commit() { asm volatile("cp.async.commit_group;" ::: "memory"); }
__device__ __forceinline__ void cpa_wait0()  { asm volatile("cp.async.wait_group 0;" ::: "memory"); }
__device__ __forceinline__ void cpa_wait1()  { asm volatile("cp.async.wait_group 1;" ::: "memory"); }

// ============================================================
// elementwise fp32 -> fp16 (hi only)
// ============================================================
__global__ __launch_bounds__(256) void splithi_ker(
    const float* __restrict__ src, unsigned* __restrict__ hi, int n4)
{
    int i = blockIdx.x * 256 + threadIdx.x;
    if (i < n4) {
        float4 v = ((const float4*)src)[i];
        ((uint2*)hi)[i] = make_uint2(hi2h(v.x, v.y), hi2h(v.z, v.w));
    }
}

// ============================================================
// GEMM: C[M,N] = A[M,1024].W[N,1024]^T, pure fp16 1-term
// CTA 128x128, BK=32, 2-stage cp.async, 8 warps (2M x 4N), 2 CTA/SM.
// Stage (20KB): Ahi@0 | Whi@10240
// Rows padded to 80B: ldmatrix conflict-free without swizzle.
// ============================================================
__device__ __forceinline__ void gemm_issue_tile(
    const unsigned* __restrict__ Ah, const unsigned* __restrict__ Wh,
    int bm, int bn, int kt, unsigned sb, int tid)
{
    const int r  = tid >> 1;          // 0..127
    const int ku = kt * 16;           // u32 col offset (BK=32 = 16 u32)
    const unsigned* g0 = Ah + (size_t)(bm + r)*512 + ku;
    const unsigned* g2 = Wh + (size_t)(bn + r)*512 + ku;
#pragma unroll
    for (int c = 0; c < 2; c++) {
        int cc = (tid & 1)*2 + c;     // chunk 0..3
        unsigned off = (unsigned)(r*80 + cc*16);
        cpa16(sb + off,          g0 + cc*4);
        cpa16(sb + 10240u + off, g2 + cc*4);
    }
}

template<int MODE>
__global__ __launch_bounds__(256, 2) void gemm_ker(
    const unsigned* __restrict__ Ahg, const unsigned* __restrict__ Whg,
    const float* __restrict__ bq, const float* __restrict__ bv,
    float* __restrict__ out)
{
    extern __shared__ unsigned smg[];
    const int tid  = threadIdx.x;
    const int lane = tid & 31;
    const int wid  = tid >> 5;
    const int wm   = wid >> 2, wn = wid & 3;
    const int qr   = lane >> 2, qc = lane & 3;
    const int j    = lane >> 3, rr = lane & 7;   // ldsm lane decomposition
    const int bm = blockIdx.y * 128, bn = blockIdx.x * 128;
    const unsigned smbase = (unsigned)__cvta_generic_to_shared(smg);

    unsigned a_off[4], b_off[2];
#pragma unroll
    for (int mt = 0; mt < 4; mt++)
        a_off[mt] = (unsigned)((wm*64 + mt*16 + ((j & 1) << 3) + rr) * 80 + (j >> 1)*16);
#pragma unroll
    for (int p = 0; p < 2; p++)
        b_off[p] = (unsigned)((wn*32 + p*16 + ((j >> 1) << 3) + rr) * 80 + (j & 1)*16);

    float acc[4][4][4];
#pragma unroll
    for (int i = 0; i < 4; i++)
#pragma unroll
        for (int jj = 0; jj < 4; jj++)
#pragma unroll
            for (int t = 0; t < 4; t++) acc[i][jj][t] = 0.f;

    gemm_issue_tile(Ahg, Whg, bm, bn, 0, smbase, tid);
    cpa_commit();

    for (int kt = 0; kt < 32; kt++) {
        if (kt + 1 < 32) {
            gemm_issue_tile(Ahg, Whg, bm, bn, kt + 1,
                            smbase + ((kt + 1) & 1) * 20480u, tid);
            cpa_commit();
            cpa_wait1();
        } else {
            cpa_wait0();
        }
        __syncthreads();

        const unsigned sA = smbase + (unsigned)(kt & 1) * 20480u;
        const unsigned sW = sA + 10240u;
#pragma unroll
        for (int ks = 0; ks < 2; ks++) {
            const unsigned ko = (unsigned)(ks * 32);
            unsigned ah[4][4], bh[4][2];
#pragma unroll
            for (int mt = 0; mt < 4; mt++)
                ldsm4(ah[mt][0], ah[mt][1], ah[mt][2], ah[mt][3], sA + a_off[mt] + ko);
#pragma unroll
            for (int p = 0; p < 2; p++)
                ldsm4(bh[2*p][0], bh[2*p][1], bh[2*p+1][0], bh[2*p+1][1], sW + b_off[p] + ko);
#pragma unroll
            for (int mt = 0; mt < 4; mt++)
#pragma unroll
                for (int nt = 0; nt < 4; nt++)
                    mmah(acc[mt][nt], ah[mt], bh[nt]);
        }
        __syncthreads();
    }

    if (MODE == 1) {
#pragma unroll
        for (int mt = 0; mt < 4; mt++)
#pragma unroll
            for (int nt = 0; nt < 4; nt++) {
                int m = bm + wm*64 + mt*16 + qr;
                int n = bn + wn*32 + nt*8 + qc*2;
                float b0 = bq[n], b1 = bq[n+1];
                *(float2*)(out + (size_t)m*Cdim + n)
                    = make_float2(acc[mt][nt][0] + b0, acc[mt][nt][1] + b1);
                *(float2*)(out + (size_t)(m+8)*Cdim + n)
                    = make_float2(acc[mt][nt][2] + b0, acc[mt][nt][3] + b1);
            }
    } else {
        const int which = bn >> 10;        // 0:q 1:k 2:v
        const int cb = bn & 1023;
#pragma unroll
        for (int mt = 0; mt < 4; mt++)
#pragma unroll
            for (int nt = 0; nt < 4; nt++) {
                int nloc = wn*32 + nt*8 + qc*2;
                int ncol = cb + nloc;
                int h = ncol >> 6, d = ncol & 63;
                float b0 = 0.f, b1 = 0.f;
                if (which == 0) { b0 = bq[ncol]; b1 = bq[ncol+1]; }
                if (which == 2) { b0 = bv[ncol]; b1 = bv[ncol+1]; }
#pragma unroll
                for (int hh = 0; hh < 2; hh++) {
                    int m = bm + wm*64 + mt*16 + qr + hh*8;
                    int b = m >> 11, l = m & (Ldim - 1);
                    float v0 = acc[mt][nt][hh*2]   + b0;
                    float v1 = acc[mt][nt][hh*2+1] + b1;
                    if (which == 2) {
                        size_t base = ((size_t)(b*Hdim + h)*64 + d)*Ldim + l;
                        g_vt[base]        = v0;
                        g_vt[base + Ldim] = v1;
                    } else {
                        float* dst = (which == 0) ? g_q : g_k;
                        *(float2*)(dst + ((size_t)(b*Hdim + h)*Ldim + l)*64 + d)
                            = make_float2(v0, v1);
                    }
                }
            }
    }
}

// ============================================================
// L2-normalize q,k rows (fp32 in place); q *= exp(min(sml[h],log100))
// ============================================================
__global__ __launch_bounds__(256) void norm_kernel(const float* __restrict__ sml)
{
    const int NR = BHL;
    int w = blockIdx.x * 8 + (threadIdx.x >> 5);
    int lane = threadIdx.x & 31;
    bool is_q = (w < NR);
    float* p = is_q ? g_q : g_k;
    int r = is_q ? w : (w - NR);
    float a0 = p[(size_t)r*64 + lane];
    float a1 = p[(size_t)r*64 + lane + 32];
    float s = a0*a0 + a1*a1;
#pragma unroll
    for (int off = 16; off > 0; off >>= 1)
        s += __shfl_xor_sync(0xffffffffu, s, off);
    float mul = 1.0f;
    if (is_q) {
        int h = (r >> 11) & (Hdim - 1);
        mul = __expf(fminf(sml[h], MAX_SCALE_MUL));
    }
    float inv = mul / fmaxf(sqrtf(s), 1e-12f);
    p[(size_t)r*64 + lane]      = a0 * inv;
    p[(size_t)r*64 + lane + 32] = a1 * inv;
}

// ============================================================
// attention tile loaders (fp32 -> fp16 hi -> swizzled smem)
// ============================================================
__device__ __forceinline__ void load_tile_hi_128x64(
    const float* __restrict__ src, size_t row0,
    unsigned* __restrict__ Hi, int tid)
{
#pragma unroll
    for (int p = 0; p < 8; p++) {
        int r = p*16 + (tid >> 4);
        int jj = tid & 15;
        const float4 v = *(const float4*)(src + (row0 + r)*64 + jj*4);
        int c = (2*jj) ^ ((r & 7) << 2);
        *(uint2*)&Hi[r*32 + c] = make_uint2(hi2h(v.x, v.y), hi2h(v.z, v.w));
    }
}

__device__ __forceinline__ void load_v_tile_hi(
    const float* __restrict__ Vg, int l0,
    unsigned* __restrict__ Hi, int tid)
{
#pragma unroll
    for (int p = 0; p < 8; p++) {
        int r = p*8 + (tid >> 5);
        int jj = tid & 31;
        const float4 v = *(const float4*)(Vg + (size_t)r*Ldim + l0 + jj*4);
        int c = (2*jj) ^ ((r & 7) << 2);
        *(uint2*)&Hi[r*64 + c] = make_uint2(hi2h(v.x, v.y), hi2h(v.z, v.w));
    }
}

// ============================================================
// Flash attention — S pass 1-term (Q,K fp16 hi); PV 2-term
// (P split, V hi). Block = (b,h) x 128-query tile, 8 warps, 48KB smem.
// smem u32: Qhi@0 Khi@4096 Vhi@8192
// ============================================================
__global__ __launch_bounds__(256) void attn_ker()
{
    extern __shared__ unsigned sma[];
    unsigned *Qhi = sma, *Khi = sma + 4096, *Vhi = sma + 8192;

    const int tid = threadIdx.x, lane = tid & 31, wid = tid >> 5;
    const int qr = lane >> 2, qc = lane & 3;
    const int bh = blockIdx.y, q0 = blockIdx.x * 128;
    const float* Qg = g_q  + (size_t)bh * Ldim * 64;
    const float* Kg = g_k  + (size_t)bh * Ldim * 64;
    const float* Vg = g_vt + (size_t)bh * 64 * Ldim;

    load_tile_hi_128x64(Qg, q0, Qhi, tid);

    float oacc[8][4];
#pragma unroll
    for (int i = 0; i < 8; i++)
#pragma unroll
        for (int t = 0; t < 4; t++) oacc[i][t] = 0.f;
    float mrow[2] = {-1e30f, -1e30f}, lrow[2] = {0.f, 0.f};

    for (int kt = 0; kt < Ldim/128; kt++) {
        __syncthreads();
        load_tile_hi_128x64(Kg, (size_t)kt*128, Khi, tid);
        load_v_tile_hi(Vg, kt*128, Vhi, tid);
        __syncthreads();

        // ---- S = Q . K^T  (1-term: qh * kh) ----
        float sacc[16][4];
#pragma unroll
        for (int i = 0; i < 16; i++)
#pragma unroll
            for (int t = 0; t < 4; t++) sacc[i][t] = 0.f;
#pragma unroll
        for (int ks = 0; ks < 4; ks++) {
            const int c0 = ks*8 + qc, c1 = c0 + 4, sw = qr << 2;
            int r0 = wid*16 + qr, r1 = r0 + 8;
            int i0 = r0*32 + (c0^sw), i1 = r1*32 + (c0^sw);
            int i2 = r0*32 + (c1^sw), i3 = r1*32 + (c1^sw);
            unsigned ah[4] = {Qhi[i0], Qhi[i1], Qhi[i2], Qhi[i3]};
#pragma unroll
            for (int g = 0; g < 2; g++) {
                unsigned bb[8][2];
#pragma unroll
                for (int t = 0; t < 8; t++) {
                    int n0 = (g*8 + t)*8 + qr;
                    bb[t][0] = Khi[n0*32 + (c0^sw)];
                    bb[t][1] = Khi[n0*32 + (c1^sw)];
                }
#pragma unroll
                for (int t = 0; t < 8; t++) mmah(sacc[g*8+t], ah, bb[t]);
            }
        }

        // ---- online softmax (quad reduce) ----
#pragma unroll
        for (int hh = 0; hh < 2; hh++) {
            float mx = -1e30f;
#pragma unroll
            for (int nt = 0; nt < 16; nt++)
                mx = fmaxf(mx, fmaxf(sacc[nt][hh*2], sacc[nt][hh*2+1]));
            mx = fmaxf(mx, __shfl_xor_sync(0xffffffffu, mx, 1));
            mx = fmaxf(mx, __shfl_xor_sync(0xffffffffu, mx, 2));
            float mnew = fmaxf(mrow[hh], mx);
            float corr = __expf(mrow[hh] - mnew);
            float rs = 0.f;
#pragma unroll
            for (int nt = 0; nt < 16; nt++) {
                float e0 = __expf(sacc[nt][hh*2]   - mnew);
                float e1 = __expf(sacc[nt][hh*2+1] - mnew);
                sacc[nt][hh*2] = e0; sacc[nt][hh*2+1] = e1;
                rs += e0 + e1;
            }
            rs += __shfl_xor_sync(0xffffffffu, rs, 1);
            rs += __shfl_xor_sync(0xffffffffu, rs, 2);
            mrow[hh] = mnew;
            lrow[hh] = lrow[hh]*corr + rs;
#pragma unroll
            for (int nt = 0; nt < 8; nt++) {
                oacc[nt][hh*2]   *= corr;
                oacc[nt][hh*2+1] *= corr;
            }
        }

        // ---- O += P . V  (P split from sacc regs; V hi only) ----
#pragma unroll
        for (int ks = 0; ks < 8; ks++) {
            unsigned ah[4], al[4];
            split2h(sacc[2*ks][0],   sacc[2*ks][1],   ah[0], al[0]);
            split2h(sacc[2*ks][2],   sacc[2*ks][3],   ah[1], al[1]);
            split2h(sacc[2*ks+1][0], sacc[2*ks+1][1], ah[2], al[2]);
            split2h(sacc[2*ks+1][2], sacc[2*ks+1][3], ah[3], al[3]);
            const int c0 = ks*8 + qc, c1 = c0 + 4, sw = qr << 2;
            unsigned bb[8][2];
#pragma unroll
            for (int nt = 0; nt < 8; nt++) {
                int n0 = nt*8 + qr;
                bb[nt][0] = Vhi[n0*64 + (c0^sw)];
                bb[nt][1] = Vhi[n0*64 + (c1^sw)];
            }
#pragma unroll
            for (int nt = 0; nt < 8; nt++) mmah(oacc[nt], al, bb[nt]);
#pragma unroll
            for (int nt = 0; nt < 8; nt++) mmah(oacc[nt], ah, bb[nt]);
        }
    }

    // ---- epilogue: normalize rows, write ctx fp16 hi ----
    const int b = bh >> 4, h = bh & 15;
    const float inv0 = 1.0f / lrow[0], inv1 = 1.0f / lrow[1];
    int q = q0 + wid*16 + qr;
#pragma unroll
    for (int nt = 0; nt < 8; nt++) {
        int du = h*32 + nt*4 + qc;    // u32 col in 512-wide row
        g_ctxhi[(size_t)(b*Ldim + q)*512 + du]
            = hi2h(oacc[nt][0]*inv0, oacc[nt][1]*inv0);
        g_ctxhi[(size_t)(b*Ldim + q + 8)*512 + du]
            = hi2h(oacc[nt][2]*inv1, oacc[nt][3]*inv1);
    }
}

// ============================================================
extern "C" void kernel_launch(void* const* d_in, const int* in_sizes, int n_in,
                              void* d_out, int out_size)
{
    const float* x     = (const float*)d_in[0];
    const float* Wqkv  = (const float*)d_in[1];
    const float* qb    = (const float*)d_in[2];
    const float* vb    = (const float*)d_in[3];
    const float* sml   = (const float*)d_in[4];
    const float* Wproj = (const float*)d_in[5];
    const float* bproj = (const float*)d_in[6];
    float* out = (float*)d_out;

    unsigned *xhi, *wqh, *wph, *chi;
    cudaGetSymbolAddress((void**)&xhi, g_xhi);
    cudaGetSymbolAddress((void**)&wqh, g_wqkvhi);
    cudaGetSymbolAddress((void**)&wph, g_wprohi);
    cudaGetSymbolAddress((void**)&chi, g_ctxhi);

    const int GEMM_SMEM = 40960;   // 2 x 20KB stages -> 2 CTA/SM
    const int ATTN_SMEM = 49152;   // 48KB
    cudaFuncSetAttribute(gemm_ker<0>, cudaFuncAttributeMaxDynamicSharedMemorySize, GEMM_SMEM);
    cudaFuncSetAttribute(gemm_ker<1>, cudaFuncAttributeMaxDynamicSharedMemorySize, GEMM_SMEM);
    cudaFuncSetAttribute(attn_ker,    cudaFuncAttributeMaxDynamicSharedMemorySize, ATTN_SMEM);

    splithi_ker<<<(Mdim*Cdim/4)/256, 256>>>(x,     xhi, Mdim*Cdim/4);
    splithi_ker<<<(3*Cdim*Cdim/4)/256, 256>>>(Wqkv, wqh, 3*Cdim*Cdim/4);
    splithi_ker<<<(Cdim*Cdim/4)/256, 256>>>(Wproj, wph, Cdim*Cdim/4);

    gemm_ker<0><<<dim3(3*Cdim/128, Mdim/128), 256, GEMM_SMEM>>>(
        xhi, wqh, qb, vb, nullptr);

    norm_kernel<<<(2*BHL)/8, 256>>>(sml);

    attn_ker<<<dim3(Ldim/128, Bdim*Hdim), 256, ATTN_SMEM>>>();

    gemm_ker<1><<<dim3(Cdim/128, Mdim/128), 256, GEMM_SMEM>>>(
        chi, wph, bproj, nullptr, out);
}